// round 4
// baseline (speedup 1.0000x reference)
#include <cuda_runtime.h>
#include <cuda_bf16.h>
#include <cstdint>

// out_means[b][d] = mean[d][labels[b][d]]; out_log_vars[b][d] = log_var[d][labels[b][d]]
// B = 2097152, N_DOMAINS = 8, MAX_CONCEPTS = 64.
// d_out: [means B*8 f32][log_vars B*8 f32].
//
// R4: 512 samples/CTA (2/thread), scalar smem tables (bank degree <=2),
// smem staging flushed with 16KB TMA bulk stores, and wait_group.READ
// (only smem-read completion, not global visibility) before CTA exit.

#define N_DOMAINS 8
#define MAX_CONCEPTS 64
#define TAB (N_DOMAINS * MAX_CONCEPTS)   // 512
#define BLK 256
#define SPT 2                            // samples per thread
#define TILE (BLK * SPT)                 // 512 samples per CTA

__global__ __launch_bounds__(BLK)
void concept_gauss_kernel(const int4* __restrict__ labels4,   // [B*2]
                          const float* __restrict__ mean,     // [512]
                          const float* __restrict__ log_var,  // [512]
                          float* __restrict__ out,            // [2*B*8]
                          int B)
{
    __shared__ float s_mean[TAB];
    __shared__ float s_var[TAB];
    __shared__ alignas(128) float st_mean[TILE * N_DOMAINS];  // 16 KB
    __shared__ alignas(128) float st_var[TILE * N_DOMAINS];   // 16 KB

    const int t = threadIdx.x;
    s_mean[t]       = mean[t];
    s_mean[t + 256] = mean[t + 256];
    s_var[t]        = log_var[t];
    s_var[t + 256]  = log_var[t + 256];
    __syncthreads();

    const long base = (long)blockIdx.x * TILE;
    const bool full_tile = (base + TILE) <= (long)B;

    const long b0 = base + t;
    const long b1 = base + t + BLK;

    if (full_tile) {
        // Front-batched label loads: MLP_p1 = 4.
        int4 a0 = __ldcs(&labels4[2 * b0]);
        int4 a1 = __ldcs(&labels4[2 * b0 + 1]);
        int4 c0 = __ldcs(&labels4[2 * b1]);
        int4 c1 = __ldcs(&labels4[2 * b1 + 1]);

        float4* pm0 = reinterpret_cast<float4*>(&st_mean[t * N_DOMAINS]);
        float4* pm1 = reinterpret_cast<float4*>(&st_mean[(t + BLK) * N_DOMAINS]);
        float4* pv0 = reinterpret_cast<float4*>(&st_var[t * N_DOMAINS]);
        float4* pv1 = reinterpret_cast<float4*>(&st_var[(t + BLK) * N_DOMAINS]);

        pm0[0] = make_float4(s_mean[0 * MAX_CONCEPTS + a0.x],
                             s_mean[1 * MAX_CONCEPTS + a0.y],
                             s_mean[2 * MAX_CONCEPTS + a0.z],
                             s_mean[3 * MAX_CONCEPTS + a0.w]);
        pm0[1] = make_float4(s_mean[4 * MAX_CONCEPTS + a1.x],
                             s_mean[5 * MAX_CONCEPTS + a1.y],
                             s_mean[6 * MAX_CONCEPTS + a1.z],
                             s_mean[7 * MAX_CONCEPTS + a1.w]);
        pm1[0] = make_float4(s_mean[0 * MAX_CONCEPTS + c0.x],
                             s_mean[1 * MAX_CONCEPTS + c0.y],
                             s_mean[2 * MAX_CONCEPTS + c0.z],
                             s_mean[3 * MAX_CONCEPTS + c0.w]);
        pm1[1] = make_float4(s_mean[4 * MAX_CONCEPTS + c1.x],
                             s_mean[5 * MAX_CONCEPTS + c1.y],
                             s_mean[6 * MAX_CONCEPTS + c1.z],
                             s_mean[7 * MAX_CONCEPTS + c1.w]);

        pv0[0] = make_float4(s_var[0 * MAX_CONCEPTS + a0.x],
                             s_var[1 * MAX_CONCEPTS + a0.y],
                             s_var[2 * MAX_CONCEPTS + a0.z],
                             s_var[3 * MAX_CONCEPTS + a0.w]);
        pv0[1] = make_float4(s_var[4 * MAX_CONCEPTS + a1.x],
                             s_var[5 * MAX_CONCEPTS + a1.y],
                             s_var[6 * MAX_CONCEPTS + a1.z],
                             s_var[7 * MAX_CONCEPTS + a1.w]);
        pv1[0] = make_float4(s_var[0 * MAX_CONCEPTS + c0.x],
                             s_var[1 * MAX_CONCEPTS + c0.y],
                             s_var[2 * MAX_CONCEPTS + c0.z],
                             s_var[3 * MAX_CONCEPTS + c0.w]);
        pv1[1] = make_float4(s_var[4 * MAX_CONCEPTS + c1.x],
                             s_var[5 * MAX_CONCEPTS + c1.y],
                             s_var[6 * MAX_CONCEPTS + c1.z],
                             s_var[7 * MAX_CONCEPTS + c1.w]);

        __syncthreads();

        if (t == 0) {
            asm volatile("fence.proxy.async.shared::cta;" ::: "memory");

            uint32_t sm_mean, sm_var;
            asm("{ .reg .u64 a; cvta.to.shared.u64 a, %1; cvt.u32.u64 %0, a; }"
                : "=r"(sm_mean) : "l"(st_mean));
            asm("{ .reg .u64 a; cvta.to.shared.u64 a, %1; cvt.u32.u64 %0, a; }"
                : "=r"(sm_var) : "l"(st_var));

            const uint32_t bytes = TILE * N_DOMAINS * sizeof(float);  // 16384
            float* dst_mean = out + base * N_DOMAINS;
            float* dst_var  = out + (long)B * N_DOMAINS + base * N_DOMAINS;

            asm volatile(
                "cp.async.bulk.global.shared::cta.bulk_group [%0], [%1], %2;"
                :: "l"(dst_mean), "r"(sm_mean), "r"(bytes) : "memory");
            asm volatile(
                "cp.async.bulk.global.shared::cta.bulk_group [%0], [%1], %2;"
                :: "l"(dst_var), "r"(sm_var), "r"(bytes) : "memory");
            asm volatile("cp.async.bulk.commit_group;" ::: "memory");
            // Only wait for TMA to finish READING smem; global visibility is
            // the memory system's problem, not this CTA's.
            asm volatile("cp.async.bulk.wait_group.read 0;" ::: "memory");
        }
        __syncthreads();   // smem must stay allocated until TMA read done
    } else {
        // Tail path: direct stores (B=2^21 is divisible by TILE, so unused,
        // but kept for safety).
        long vb = 2L * B;  // float4 units
        float4* o = reinterpret_cast<float4*>(out);
        for (int s = 0; s < SPT; s++) {
            long b = base + t + (long)s * BLK;
            if (b >= B) break;
            int4 l0 = __ldcs(&labels4[2 * b]);
            int4 l1 = __ldcs(&labels4[2 * b + 1]);
            o[2 * b]     = make_float4(s_mean[0 * MAX_CONCEPTS + l0.x],
                                       s_mean[1 * MAX_CONCEPTS + l0.y],
                                       s_mean[2 * MAX_CONCEPTS + l0.z],
                                       s_mean[3 * MAX_CONCEPTS + l0.w]);
            o[2 * b + 1] = make_float4(s_mean[4 * MAX_CONCEPTS + l1.x],
                                       s_mean[5 * MAX_CONCEPTS + l1.y],
                                       s_mean[6 * MAX_CONCEPTS + l1.z],
                                       s_mean[7 * MAX_CONCEPTS + l1.w]);
            o[vb + 2 * b]     = make_float4(s_var[0 * MAX_CONCEPTS + l0.x],
                                            s_var[1 * MAX_CONCEPTS + l0.y],
                                            s_var[2 * MAX_CONCEPTS + l0.z],
                                            s_var[3 * MAX_CONCEPTS + l0.w]);
            o[vb + 2 * b + 1] = make_float4(s_var[4 * MAX_CONCEPTS + l1.x],
                                            s_var[5 * MAX_CONCEPTS + l1.y],
                                            s_var[6 * MAX_CONCEPTS + l1.z],
                                            s_var[7 * MAX_CONCEPTS + l1.w]);
        }
    }
}

extern "C" void kernel_launch(void* const* d_in, const int* in_sizes, int n_in,
                              void* d_out, int out_size) {
    const int4*  labels4 = (const int4*)d_in[0];
    const float* mean    = (const float*)d_in[1];
    const float* log_var = (const float*)d_in[2];
    float* out = (float*)d_out;

    int B = in_sizes[0] / N_DOMAINS;     // 2097152
    int blocks = (B + TILE - 1) / TILE;  // 4096
    concept_gauss_kernel<<<blocks, BLK>>>(labels4, mean, log_var, out, B);
}